// round 16
// baseline (speedup 1.0000x reference)
#include <cuda_runtime.h>
#include <cuda_bf16.h>
#include <cuda_fp16.h>
#include <math.h>
#include <stdint.h>

// Problem constants
#define BDIM 2
#define SDIM 2048
#define DDIM 1024
#define HH   8
#define MROWS (BDIM*SDIM)          // 4096
static __device__ __constant__ float LAMBDA_INIT_F = 0.470713018343584f; // 0.8 - 0.6*exp(-0.6)

// ================= scratch (device globals) =================
__device__ float g_lambda;
__device__ __half g_qkv16[MROWS * 3 * DDIM];
__device__ float g_tmp1[MROWS * DDIM];
__device__ float g_h   [MROWS * DDIM];
__device__ float g_f2  [MROWS * DDIM];

// attention operands: plain fp16, [b,h,s,64] / [b,h,s,128]
#define QKELEM (BDIM*HH*SDIM*64)
__device__ __half g_q116[QKELEM], g_k116[QKELEM];
__device__ __half g_q216[QKELEM], g_k216[QKELEM];
__device__ __half g_v16[BDIM*HH*SDIM*128];

// fp16 staging (all weights plain single-term)
__device__ __half g_x16  [MROWS*DDIM];
__device__ __half g_attn16[MROWS*DDIM];
__device__ __half g_h16  [MROWS*DDIM];
__device__ __half g_ff116[MROWS*4*DDIM];
__device__ __half g_wqkvT16[3*DDIM*DDIM];
__device__ __half g_woutT16[DDIM*DDIM];
__device__ __half g_w1T16[4*DDIM*DDIM];
__device__ __half g_w2T16[DDIM*4*DDIM];

// ================= helpers =================
__device__ __forceinline__ uint32_t smem_u32(const void* p) {
    uint32_t a;
    asm("{ .reg .u64 t; cvta.to.shared.u64 t, %1; cvt.u32.u64 %0, t; }" : "=r"(a) : "l"(p));
    return a;
}
__device__ __forceinline__ void cpasync16(uint32_t dst, const void* src) {
    asm volatile("cp.async.cg.shared.global [%0], [%1], 16;" :: "r"(dst), "l"(src));
}
__device__ __forceinline__ void cp_commit() { asm volatile("cp.async.commit_group;" ::: "memory"); }
__device__ __forceinline__ void ldm4(uint32_t* r, uint32_t addr) {
    asm volatile("ldmatrix.sync.aligned.m8n8.x4.shared.b16 {%0,%1,%2,%3}, [%4];"
        : "=r"(r[0]), "=r"(r[1]), "=r"(r[2]), "=r"(r[3]) : "r"(addr));
}
__device__ __forceinline__ void ldm4t(uint32_t* r, uint32_t addr) {
    asm volatile("ldmatrix.sync.aligned.m8n8.x4.trans.shared.b16 {%0,%1,%2,%3}, [%4];"
        : "=r"(r[0]), "=r"(r[1]), "=r"(r[2]), "=r"(r[3]) : "r"(addr));
}
__device__ __forceinline__ void mma16816h(float* c, const uint32_t* a, uint32_t b0, uint32_t b1) {
    asm volatile("mma.sync.aligned.m16n8k16.row.col.f32.f16.f16.f32 "
        "{%0,%1,%2,%3}, {%4,%5,%6,%7}, {%8,%9}, {%0,%1,%2,%3};"
        : "+f"(c[0]), "+f"(c[1]), "+f"(c[2]), "+f"(c[3])
        : "r"(a[0]), "r"(a[1]), "r"(a[2]), "r"(a[3]), "r"(b0), "r"(b1));
}
__device__ __forceinline__ uint32_t packh(float a, float b) {
    __half2 t = __floats2half2_rn(a, b);
    return *(uint32_t*)&t;
}

// ================= lambda =================
__global__ void lambda_kernel(const float* __restrict__ lq1, const float* __restrict__ lk1,
                              const float* __restrict__ lq2, const float* __restrict__ lk2)
{
    int lane = threadIdx.x;
    float s1 = lq1[lane]*lk1[lane] + lq1[lane+32]*lk1[lane+32];
    float s2 = lq2[lane]*lk2[lane] + lq2[lane+32]*lk2[lane+32];
#pragma unroll
    for (int o = 16; o; o >>= 1) {
        s1 += __shfl_xor_sync(0xffffffffu, s1, o);
        s2 += __shfl_xor_sync(0xffffffffu, s2, o);
    }
    if (lane == 0) g_lambda = expf(s1) - expf(s2) + LAMBDA_INIT_F;
}

// ================= fp32 -> plain fp16 =================
__global__ __launch_bounds__(256) void split_f16_kernel(const float* __restrict__ in,
    __half* __restrict__ o, int n4)
{
    int i = blockIdx.x * 256 + threadIdx.x;
    if (i >= n4) return;
    float4 v = ((const float4*)in)[i];
    ((__half2*)o)[2*i]   = __floats2half2_rn(v.x, v.y);
    ((__half2*)o)[2*i+1] = __floats2half2_rn(v.z, v.w);
}

// ================= transpose: in[K,N] fp32 -> out[N,K] fp16 =================
__global__ __launch_bounds__(256) void transpose_f16_kernel(const float* __restrict__ in,
    __half* __restrict__ oh, int K, int N)
{
    __shared__ float t[32][33];
    const int k0 = blockIdx.y*32, n0 = blockIdx.x*32;
    const int tx = threadIdx.x, ty = threadIdx.y;
#pragma unroll
    for (int i = 0; i < 4; i++)
        t[ty + i*8][tx] = in[(size_t)(k0 + ty + i*8)*N + n0 + tx];
    __syncthreads();
#pragma unroll
    for (int i = 0; i < 4; i++) {
        int n = n0 + ty + i*8, k = k0 + tx;
        oh[(size_t)n*K + k] = __float2half(t[tx][ty + i*8]);
    }
}

// ================= mma.sync fp16 GEMM (R12 shape + batched A-fragment ldsm) =============
// C[M,N] = A[M,K] @ B[N,K]^T (+bias)(silu?)(+resid)
// 256 thr, 2m x 4n warps of 64x32. K-chunk 64 (144B stride), 2-stage, one barrier/chunk.
#define FK_ROWB   144
#define F_TILE_B  (128*FK_ROWB)     // 18432
#define F_STAGE_B (2*F_TILE_B)      // 36864
#define GEMMF_SMEM (2*F_STAGE_B)    // 73728

__global__ __launch_bounds__(256, 2) void gemm_f16_kernel(
    const __half* __restrict__ Ah,
    const __half* __restrict__ Bh,
    float* __restrict__ Cf, __half* __restrict__ Ch16,
    int M, int N, int K,
    const float* __restrict__ bias, const float* __restrict__ resid, int act)
{
    extern __shared__ char smem[];
    const uint32_t sb = smem_u32(smem);
    const int tid = threadIdx.x;
    const int lane = tid & 31;
    const int wid = tid >> 5;
    const int bm = blockIdx.y * 128;
    const int bn = blockIdx.x * 128;
    const int wm = wid >> 2;
    const int wn = wid & 3;

    const int lrow  = tid >> 1;
    const int lhalf = (tid & 1) * 64;
    const size_t rowB = (size_t)K * 2;
    const char* gA  = (const char*)Ah + (size_t)(bm + lrow) * rowB + lhalf;
    const char* gBh = (const char*)Bh + (size_t)(bn + lrow) * rowB + lhalf;
    const uint32_t sdst = sb + (uint32_t)lrow * FK_ROWB + (uint32_t)lhalf;

    const int nChunks = K >> 6;

    {
#pragma unroll
        for (int j = 0; j < 4; j++) {
            cpasync16(sdst +            j*16, gA  + j*16);
            cpasync16(sdst + F_TILE_B + j*16, gBh + j*16);
        }
        cp_commit();
    }

    float acc[4][4][4];
#pragma unroll
    for (int i = 0; i < 4; i++)
#pragma unroll
        for (int j = 0; j < 4; j++)
#pragma unroll
            for (int k = 0; k < 4; k++) acc[i][j][k] = 0.f;

    const int lt = lane >> 3, lj = lane & 7;
    const uint32_t a_row = (uint32_t)(wm*64 + (lt & 1)*8 + lj) * FK_ROWB;
    const uint32_t a_col = (uint32_t)((lt >> 1) * 8) * 2u;
    const uint32_t b_row = (uint32_t)(wn*32 + (lt >> 1)*8 + lj) * FK_ROWB;
    const uint32_t b_col = (uint32_t)((lt & 1) * 8) * 2u;

    for (int c = 0; c < nChunks; c++) {
        asm volatile("cp.async.wait_group 0;" ::: "memory");
        __syncthreads();

        if (c + 1 < nChunks) {
            const uint32_t d = sdst + (uint32_t)((c + 1) & 1) * F_STAGE_B;
            const size_t go = (size_t)(c + 1) * 128;
#pragma unroll
            for (int j = 0; j < 4; j++) {
                cpasync16(d +            j*16, gA  + go + j*16);
                cpasync16(d + F_TILE_B + j*16, gBh + go + j*16);
            }
            cp_commit();
        }

        const uint32_t base = sb + (uint32_t)(c & 1) * F_STAGE_B;
#pragma unroll
        for (int ka = 0; ka < 4; ka++) {
            const uint32_t kofs = (uint32_t)ka * 32u;
            // batch all fragment loads for this ka so the 6 ldsm pipeline
            uint32_t bfh[2][4];
#pragma unroll
            for (int g = 0; g < 2; g++)
                ldm4(bfh[g], base + F_TILE_B + b_row + (uint32_t)g*16u*FK_ROWB + b_col + kofs);
            uint32_t af[4][4];
#pragma unroll
            for (int ma = 0; ma < 4; ma++)
                ldm4(af[ma], base + a_row + (uint32_t)ma*16u*FK_ROWB + a_col + kofs);
#pragma unroll
            for (int ma = 0; ma < 4; ma++)
#pragma unroll
                for (int g = 0; g < 2; g++)
#pragma unroll
                    for (int hf = 0; hf < 2; hf++)
                        mma16816h(acc[ma][g*2 + hf], af[ma], bfh[g][hf*2], bfh[g][hf*2+1]);
        }
    }

#pragma unroll
    for (int ma = 0; ma < 4; ma++)
#pragma unroll
        for (int na = 0; na < 4; na++) {
            const int r0 = bm + wm*64 + ma*16 + (lane >> 2);
            const int c0 = bn + wn*32 + na*8 + 2*(lane & 3);
#pragma unroll
            for (int half = 0; half < 2; half++) {
                const int r = r0 + half*8;
                float v0 = acc[ma][na][half*2 + 0];
                float v1 = acc[ma][na][half*2 + 1];
                if (bias) { v0 += bias[c0]; v1 += bias[c0 + 1]; }
                if (act) {
                    v0 = v0 / (1.f + __expf(-v0));
                    v1 = v1 / (1.f + __expf(-v1));
                }
                const size_t o = (size_t)r * N + c0;
                if (resid) { v0 += resid[o]; v1 += resid[o + 1]; }
                if (Cf) { float2 f2o; f2o.x = v0; f2o.y = v1; *(float2*)&Cf[o] = f2o; }
                if (Ch16) *(__half2*)&Ch16[o] = __floats2half2_rn(v0, v1);
            }
        }
}

// ================= RoPE + head split + q2/k2 rmsnorm + V repack (fp16 in/out) ======
__global__ __launch_bounds__(256) void rope_split_kernel(
    const float* __restrict__ sigmas, const float* __restrict__ lnq_w, const float* __restrict__ lnq_b)
{
    const int row = blockIdx.x;
    const int b = row / SDIM, s = row % SDIM;
    const __half* base = g_qkv16 + (size_t)row * 3072;
    const int lane = threadIdx.x & 31;
    const int warp = threadIdx.x >> 5;

    // V repack: vectorized uint4 (16B) copies. Row has 1024 halves = 128 uint4.
    // dst per head: 128 halves = 16 uint4, base aligned to 256B.
    {
        const uint4* src = (const uint4*)(base + 2048);
        for (int idx = threadIdx.x; idx < 128; idx += 256) {
            int h = idx >> 4, e = idx & 15;   // e in uint4 units within head
            uint4* dst = (uint4*)(g_v16 + (((size_t)b*HH + h)*SDIM + s)*128);
            dst[e] = src[idx];
        }
    }

    int p = lane >> 1;
    float inv = (float)exp(-(double)p * 0.57564627324851148);
    float fr = (float)s * inv;
    float c0 = cosf(fr), s0 = sinf(fr);

    for (int t = warp; t < 32; t += 8) {
        const int which = t >> 4;
        const int h2 = t & 15;
        const __half* src = base + which*1024 + h2*64;
        float x0 = __half2float(src[lane]);
        float x1 = __half2float(src[lane + 32]);
        float partner = __half2float(src[lane ^ 1]);
        float r0 = (lane & 1) ? fmaf(x0, c0,  partner * s0)
                              : fmaf(x0, c0, -partner * s0);
        const int h = h2 >> 1, comp = h2 & 1;
        size_t off = (((size_t)b*HH + h)*SDIM + s)*64;
        if (comp == 0) {
            __half* dst = which ? g_k116 : g_q116;
            dst[off + lane]      = __float2half(r0);
            dst[off + lane + 32] = __float2half(x1);
        } else {
            float a0 = r0 + sigmas[b*64 + lane];
            float a1 = x1 + sigmas[b*64 + lane + 32];
            float ss = a0*a0 + a1*a1;
#pragma unroll
            for (int o = 16; o; o >>= 1) ss += __shfl_xor_sync(0xffffffffu, ss, o);
            float rms = rsqrtf(ss * (1.f/64.f) + 1e-8f);
            float v0 = fmaf(a0*rms, lnq_w[lane],      lnq_b[lane]);
            float v1 = fmaf(a1*rms, lnq_w[lane+32],   lnq_b[lane+32]);
            __half* dst = which ? g_k216 : g_q216;
            dst[off + lane]      = __float2half(v0);
            dst[off + lane + 32] = __float2half(v1);
        }
    }
}

// ================= tensor-core dual causal attention (plain fp16) + diff + rmsnorm =======
#define AKT_STRIDE 144
#define AVT_STRIDE 272
#define AQ_TILE 9216
#define AV_TILE 17408
#define A_QREG (2*AQ_TILE)               // 18432
#define AKV_STAGE (2*AQ_TILE + AV_TILE)  // 35840
#define ATT_SMEM (A_QREG + 2*AKV_STAGE)  // 90112
#define SCALE_L2E 0.18033688011112042f   // 0.125 * log2(e)

__global__ __launch_bounds__(256, 2) void attn_mma_kernel(
    const float* __restrict__ ln_w, const float* __restrict__ ln_b)
{
    extern __shared__ char smem[];
    const uint32_t sb = smem_u32(smem);
    const int tid = threadIdx.x, lane = tid & 31, wid = tid >> 5;
    const int br = wid >> 2, wr = wid & 3;
    const int qt = (int)gridDim.x - 1 - (int)blockIdx.x;   // heavy tiles first
    const int h = blockIdx.y, b = blockIdx.z;
    const int q0 = qt * 64;
    const int bh = b*HH + h;
    const size_t qkbase = (size_t)bh * SDIM * 64;
    const size_t vbase  = (size_t)bh * SDIM * 128;

    // prologue: Q tiles + stage 0 K/V
    {
        const int rq = (tid >> 3), jq = tid & 7;
#pragma unroll
        for (int u = 0; u < 4; u++) {
            const int row = rq + (u & 1)*32;
            const __half* src = (u < 2) ? g_q116 : g_q216;
            cpasync16(sb + (u >> 1)*AQ_TILE + row*AKT_STRIDE + jq*16,
                      src + qkbase + (size_t)(q0 + row)*64 + jq*8);
        }
        const uint32_t kb = sb + A_QREG;
#pragma unroll
        for (int u = 0; u < 4; u++) {
            const int row = rq + (u & 1)*32;
            const __half* src = (u < 2) ? g_k116 : g_k216;
            cpasync16(kb + (u >> 1)*AQ_TILE + row*AKT_STRIDE + jq*16,
                      src + qkbase + (size_t)row*64 + jq*8);
        }
        const uint32_t vb = kb + 2*AQ_TILE;
        const int rv = (tid >> 4), jv = tid & 15;
#pragma unroll
        for (int u = 0; u < 4; u++) {
            const int row = rv + u*16;
            cpasync16(vb + row*AVT_STRIDE + jv*16,
                      g_v16 + vbase + (size_t)row*128 + jv*8);
        }
        cp_commit();
    }

    const int lt = lane >> 3, lj = lane & 7;
    const uint32_t qa_off = (uint32_t)(wr*16 + (lt & 1)*8 + lj)*AKT_STRIDE + (uint32_t)(lt >> 1)*16;
    const uint32_t kb_off = (uint32_t)((lt >> 1)*8 + lj)*AKT_STRIDE + (uint32_t)(lt & 1)*16;
    const uint32_t vb_off = (uint32_t)((lt & 1)*8 + lj)*AVT_STRIDE + (uint32_t)(lt >> 1)*16;
    const uint32_t qbase = sb + br*AQ_TILE;

    float acc[16][4];
#pragma unroll
    for (int n = 0; n < 16; n++)
#pragma unroll
        for (int c = 0; c < 4; c++) acc[n][c] = 0.f;
    float m0 = -1e30f, m1 = -1e30f, l0 = 0.f, l1 = 0.f;

    const int row_l = wr*16 + (lane >> 2);
    const int nIter = qt + 1;

    for (int kt = 0; kt < nIter; kt++) {
        if (kt + 1 < nIter) {
            const int k0n = (kt + 1) * 64;
            const uint32_t kb = sb + A_QREG + ((kt + 1) & 1)*AKV_STAGE;
            const int rq = (tid >> 3), jq = tid & 7;
#pragma unroll
            for (int u = 0; u < 4; u++) {
                const int row = rq + (u & 1)*32;
                const __half* src = (u < 2) ? g_k116 : g_k216;
                cpasync16(kb + (u >> 1)*AQ_TILE + row*AKT_STRIDE + jq*16,
                          src + qkbase + (size_t)(k0n + row)*64 + jq*8);
            }
            const uint32_t vb = kb + 2*AQ_TILE;
            const int rv = (tid >> 4), jv = tid & 15;
#pragma unroll
            for (int u = 0; u < 4; u++) {
                const int row = rv + u*16;
                cpasync16(vb + row*AVT_STRIDE + jv*16,
                          g_v16 + vbase + (size_t)(k0n + row)*128 + jv*8);
            }
            cp_commit();
            asm volatile("cp.async.wait_group 1;" ::: "memory");
        } else {
            asm volatile("cp.async.wait_group 0;" ::: "memory");
        }
        __syncthreads();

        const uint32_t stg = sb + A_QREG + (kt & 1)*AKV_STAGE;
        const uint32_t k_base = stg + br*AQ_TILE;
        const uint32_t v_base = stg + 2*AQ_TILE;

        float sacc[8][4];
#pragma unroll
        for (int g = 0; g < 8; g++)
#pragma unroll
            for (int c = 0; c < 4; c++) sacc[g][c] = 0.f;
#pragma unroll
        for (int ka = 0; ka < 4; ka++) {
            uint32_t ah[4];
            ldm4(ah, qbase + qa_off + ka*32);
#pragma unroll
            for (int g2 = 0; g2 < 4; g2++) {
                uint32_t bh4[4];
                ldm4(bh4, k_base + g2*(16*AKT_STRIDE) + kb_off + ka*32);
#pragma unroll
                for (int hf = 0; hf < 2; hf++)
                    mma16816h(sacc[g2*2 + hf], ah, bh4[hf*2], bh4[hf*2+1]);
            }
        }

        const bool diag = (kt == qt);
        float t0 = -1e30f, t1 = -1e30f;
#pragma unroll
        for (int g = 0; g < 8; g++) {
            const int cb = g*8 + (lane & 3)*2;
#pragma unroll
            for (int c = 0; c < 4; c++) {
                float s = sacc[g][c] * SCALE_L2E;
                if (diag) {
                    const int rr = row_l + (c >= 2 ? 8 : 0);
                    const int cc = cb + (c & 1);
                    if (cc > rr) s = -1e30f;
                }
                sacc[g][c] = s;
            }
            t0 = fmaxf(t0, fmaxf(sacc[g][0], sacc[g][1]));
            t1 = fmaxf(t1, fmaxf(sacc[g][2], sacc[g][3]));
        }
        t0 = fmaxf(t0, __shfl_xor_sync(0xffffffffu, t0, 1));
        t0 = fmaxf(t0, __shfl_xor_sync(0xffffffffu, t0, 2));
        t1 = fmaxf(t1, __shfl_xor_sync(0xffffffffu, t1, 1));
        t1 = fmaxf(t1, __shfl_xor_sync(0xffffffffu, t1, 2));
        const float mn0 = fmaxf(m0, t0), mn1 = fmaxf(m1, t1);
        const float alpha0 = exp2f(m0 - mn0), alpha1 = exp2f(m1 - mn1);
        m0 = mn0; m1 = mn1;

        float rs0 = 0.f, rs1 = 0.f;
#pragma unroll
        for (int g = 0; g < 8; g++) {
            float p0 = exp2f(sacc[g][0] - mn0);
            float p1 = exp2f(sacc[g][1] - mn0);
            float p2 = exp2f(sacc[g][2] - mn1);
            float p3 = exp2f(sacc[g][3] - mn1);
            sacc[g][0] = p0; sacc[g][1] = p1; sacc[g][2] = p2; sacc[g][3] = p3;
            rs0 += p0 + p1; rs1 += p2 + p3;
        }
        rs0 += __shfl_xor_sync(0xffffffffu, rs0, 1);
        rs0 += __shfl_xor_sync(0xffffffffu, rs0, 2);
        rs1 += __shfl_xor_sync(0xffffffffu, rs1, 1);
        rs1 += __shfl_xor_sync(0xffffffffu, rs1, 2);
        l0 = l0*alpha0 + rs0;
        l1 = l1*alpha1 + rs1;

#pragma unroll
        for (int n = 0; n < 16; n++) {
            acc[n][0] *= alpha0; acc[n][1] *= alpha0;
            acc[n][2] *= alpha1; acc[n][3] *= alpha1;
        }

#pragma unroll
        for (int ka = 0; ka < 4; ka++) {
            uint32_t ph[4];
#pragma unroll
            for (int half = 0; half < 2; half++) {
                const int g = 2*ka + half;
                ph[half*2 + 0] = packh(sacc[g][0], sacc[g][1]);
                ph[half*2 + 1] = packh(sacc[g][2], sacc[g][3]);
            }
#pragma unroll
            for (int np = 0; np < 8; np++) {
                uint32_t vh4[4];
                ldm4t(vh4, v_base + ka*(16*AVT_STRIDE) + vb_off + np*32);
#pragma unroll
                for (int hf = 0; hf < 2; hf++)
                    mma16816h(acc[np*2 + hf], ph, vh4[hf*2], vh4[hf*2+1]);
            }
        }
        __syncthreads();
    }

    const float inv0 = 1.f / l0, inv1 = 1.f / l1;
#pragma unroll
    for (int n = 0; n < 16; n++) {
        acc[n][0] *= inv0; acc[n][1] *= inv0;
        acc[n][2] *= inv1; acc[n][3] *= inv1;
    }

    float* sO = (float*)smem;
    const int rl = row_l, rh = row_l + 8;
    __syncthreads();
    if (br == 1) {
#pragma unroll
        for (int n = 0; n < 16; n++) {
            const int c = n*8 + (lane & 3)*2;
            float2 a; a.x = acc[n][0]; a.y = acc[n][1];
            float2 bvv; bvv.x = acc[n][2]; bvv.y = acc[n][3];
            *(float2*)&sO[rl*128 + c] = a;
            *(float2*)&sO[rh*128 + c] = bvv;
        }
    }
    __syncthreads();
    if (br == 0) {
        const float lam = g_lambda;
        const float osc = 1.f - LAMBDA_INIT_F;
        float ssq0 = 0.f, ssq1 = 0.f;
#pragma unroll
        for (int n = 0; n < 16; n++) {
            const int c = n*8 + (lane & 3)*2;
            float2 o2l = *(float2*)&sO[rl*128 + c];
            float2 o2h = *(float2*)&sO[rh*128 + c];
            acc[n][0] -= lam*o2l.x; acc[n][1] -= lam*o2l.y;
            acc[n][2] -= lam*o2h.x; acc[n][3] -= lam*o2h.y;
            ssq0 += acc[n][0]*acc[n][0] + acc[n][1]*acc[n][1];
            ssq1 += acc[n][2]*acc[n][2] + acc[n][3]*acc[n][3];
        }
        ssq0 += __shfl_xor_sync(0xffffffffu, ssq0, 1);
        ssq0 += __shfl_xor_sync(0xffffffffu, ssq0, 2);
        ssq1 += __shfl_xor_sync(0xffffffffu, ssq1, 1);
        ssq1 += __shfl_xor_sync(0xffffffffu, ssq1, 2);
        const float rms0 = rsqrtf(ssq0 * (1.f/128.f) + 1e-8f);
        const float rms1 = rsqrtf(ssq1 * (1.f/128.f) + 1e-8f);
        const size_t ob_l = ((size_t)(b*SDIM + q0 + rl))*DDIM + h*128;
        const size_t ob_h = ((size_t)(b*SDIM + q0 + rh))*DDIM + h*128;
#pragma unroll
        for (int n = 0; n < 16; n++) {
            const int c = n*8 + (lane & 3)*2;
            float w0 = __ldg(&ln_w[c]), w1 = __ldg(&ln_w[c+1]);
            float bb0 = __ldg(&ln_b[c]), bb1 = __ldg(&ln_b[c+1]);
            float v0 = (acc[n][0]*rms0*w0 + bb0) * osc;
            float v1 = (acc[n][1]*rms0*w1 + bb1) * osc;
            float v2 = (acc[n][2]*rms1*w0 + bb0) * osc;
            float v3 = (acc[n][3]*rms1*w1 + bb1) * osc;
            *(__half2*)&g_attn16[ob_l + c] = __floats2half2_rn(v0, v1);
            *(__half2*)&g_attn16[ob_h + c] = __floats2half2_rn(v2, v3);
        }
    }
}

// ================= layernorm over 1024 (+ optional plain fp16 out) =================
__global__ __launch_bounds__(256) void layernorm_kernel(
    const float* __restrict__ in, const float* __restrict__ w, const float* __restrict__ bb,
    float* __restrict__ out, __half* __restrict__ oh16)
{
    __shared__ float red1[8], red2[8];
    const int row = blockIdx.x;
    const float* x = in + (size_t)row * DDIM;
    float v[4];
    float s = 0.f, s2 = 0.f;
#pragma unroll
    for (int it = 0; it < 4; it++) {
        float t = x[threadIdx.x + it*256];
        v[it] = t; s += t; s2 += t*t;
    }
#pragma unroll
    for (int o = 16; o; o >>= 1) {
        s  += __shfl_xor_sync(0xffffffffu, s,  o);
        s2 += __shfl_xor_sync(0xffffffffu, s2, o);
    }
    const int lane = threadIdx.x & 31, wp = threadIdx.x >> 5;
    if (lane == 0) { red1[wp] = s; red2[wp] = s2; }
    __syncthreads();
    if (wp == 0) {
        s  = (lane < 8) ? red1[lane] : 0.f;
        s2 = (lane < 8) ? red2[lane] : 0.f;
#pragma unroll
        for (int o = 4; o; o >>= 1) {
            s  += __shfl_xor_sync(0xffffffffu, s,  o);
            s2 += __shfl_xor_sync(0xffffffffu, s2, o);
        }
        if (lane == 0) { red1[0] = s * (1.f/1024.f); red2[0] = s2 * (1.f/1024.f); }
    }
    __syncthreads();
    const float mean = red1[0];
    const float var = red2[0] - mean*mean;
    const float rstd = rsqrtf(var + 1e-5f);
#pragma unroll
    for (int it = 0; it < 4; it++) {
        int c = threadIdx.x + it*256;
        size_t idx = (size_t)row*DDIM + c;
        float y = (v[it] - mean)*rstd*w[c] + bb[c];
        out[idx] = y;
        if (oh16) oh16[idx] = __float2half(y);
    }
}

// ================= launch =================
extern "C" void kernel_launch(void* const* d_in, const int* in_sizes, int n_in,
                              void* d_out, int out_size)
{
    (void)in_sizes; (void)n_in; (void)out_size;
    const float* x      = (const float*)d_in[0];
    const float* sigmas = (const float*)d_in[1];
    const float* w_qkv  = (const float*)d_in[2];
    const float* w_out  = (const float*)d_in[3];
    const float* lq1    = (const float*)d_in[4];
    const float* lk1    = (const float*)d_in[5];
    const float* lq2    = (const float*)d_in[6];
    const float* lk2    = (const float*)d_in[7];
    const float* ln_w   = (const float*)d_in[8];
    const float* ln_b   = (const float*)d_in[9];
    const float* lnq_w  = (const float*)d_in[10];
    const float* lnq_b  = (const float*)d_in[11];
    const float* ln1_w  = (const float*)d_in[12];
    const float* ln1_b  = (const float*)d_in[13];
    const float* ln2_w  = (const float*)d_in[14];
    const float* ln2_b  = (const float*)d_in[15];
    const float* w1     = (const float*)d_in[16];
    const float* b1     = (const float*)d_in[17];
    const float* w2     = (const float*)d_in[18];
    const float* b2     = (const float*)d_in[19];
    float* out = (float*)d_out;

    void *p_qkv16, *p_tmp1, *p_h, *p_f2;
    void *p_x16, *p_attn16, *p_h16, *p_ff116;
    void *p_wqkv, *p_wout, *p_w1, *p_w2;
    cudaGetSymbolAddress(&p_qkv16, g_qkv16);
    cudaGetSymbolAddress(&p_tmp1, g_tmp1);
    cudaGetSymbolAddress(&p_h,    g_h);
    cudaGetSymbolAddress(&p_f2,   g_f2);
    cudaGetSymbolAddress(&p_x16, g_x16);
    cudaGetSymbolAddress(&p_attn16, g_attn16);
    cudaGetSymbolAddress(&p_h16, g_h16);
    cudaGetSymbolAddress(&p_ff116, g_ff116);
    cudaGetSymbolAddress(&p_wqkv, g_wqkvT16);
    cudaGetSymbolAddress(&p_wout, g_woutT16);
    cudaGetSymbolAddress(&p_w1, g_w1T16);
    cudaGetSymbolAddress(&p_w2, g_w2T16);

    cudaFuncSetAttribute(gemm_f16_kernel, cudaFuncAttributeMaxDynamicSharedMemorySize, GEMMF_SMEM);
    cudaFuncSetAttribute(attn_mma_kernel, cudaFuncAttributeMaxDynamicSharedMemorySize, ATT_SMEM);

    // prep for qkv
    lambda_kernel<<<1, 32>>>(lq1, lk1, lq2, lk2);
    split_f16_kernel<<<(MROWS*DDIM/4 + 255)/256, 256>>>(x, (__half*)p_x16, MROWS*DDIM/4);
    transpose_f16_kernel<<<dim3(3072/32, 1024/32), dim3(32,8)>>>(w_qkv, (__half*)p_wqkv, 1024, 3072);

    // qkv = x @ w_qkv -> fp16 directly
    gemm_f16_kernel<<<dim3(3072/128, 4096/128), 256, GEMMF_SMEM>>>(
        (const __half*)p_x16, (const __half*)p_wqkv,
        nullptr, (__half*)p_qkv16, MROWS, 3072, 1024, nullptr, nullptr, 0);

    rope_split_kernel<<<MROWS, 256>>>(sigmas, lnq_w, lnq_b);

    attn_mma_kernel<<<dim3(SDIM/64, HH, BDIM), 256, ATT_SMEM>>>(ln_w, ln_b);

    // remaining weight transposes
    transpose_f16_kernel<<<dim3(1024/32, 1024/32), dim3(32,8)>>>(w_out, (__half*)p_wout, 1024, 1024);
    transpose_f16_kernel<<<dim3(4096/32, 1024/32), dim3(32,8)>>>(w1, (__half*)p_w1, 1024, 4096);
    transpose_f16_kernel<<<dim3(1024/32, 4096/32), dim3(32,8)>>>(w2, (__half*)p_w2, 4096, 1024);

    // tmp1 = attn @ w_out + x
    gemm_f16_kernel<<<dim3(1024/128, 4096/128), 256, GEMMF_SMEM>>>(
        (const __half*)p_attn16, (const __half*)p_wout,
        (float*)p_tmp1, nullptr, MROWS, 1024, 1024, nullptr, x, 0);

    layernorm_kernel<<<MROWS, 256>>>((const float*)p_tmp1, ln1_w, ln1_b,
        (float*)p_h, (__half*)p_h16);

    // ff1 = silu(h @ w1 + b1)
    gemm_f16_kernel<<<dim3(4096/128, 4096/128), 256, GEMMF_SMEM>>>(
        (const __half*)p_h16, (const __half*)p_w1,
        nullptr, (__half*)p_ff116, MROWS, 4096, 1024, b1, nullptr, 1);

    // f2 = ff1 @ w2 + b2 + h
    gemm_f16_kernel<<<dim3(1024/128, 4096/128), 256, GEMMF_SMEM>>>(
        (const __half*)p_ff116, (const __half*)p_w2,
        (float*)p_f2, nullptr, MROWS, 1024, 4096, b2, (const float*)p_h, 0);

    layernorm_kernel<<<MROWS, 256>>>((const float*)p_f2, ln2_w, ln2_b, out, nullptr);
}

// round 17
// speedup vs baseline: 1.0196x; 1.0196x over previous
#include <cuda_runtime.h>
#include <cuda_bf16.h>
#include <cuda_fp16.h>
#include <math.h>
#include <stdint.h>

// Problem constants
#define BDIM 2
#define SDIM 2048
#define DDIM 1024
#define HH   8
#define MROWS (BDIM*SDIM)          // 4096
static __device__ __constant__ float LAMBDA_INIT_F = 0.470713018343584f; // 0.8 - 0.6*exp(-0.6)

// invfreq[j] = 10000^(-j/16), j = 0..15  (RoPE, ROT=32)
static __device__ __constant__ float INVFREQ[16] = {
    1.0f, 0.5623413251903491f, 0.31622776601683794f, 0.17782794100389228f,
    0.1f, 0.05623413251903491f, 0.031622776601683794f, 0.017782794100389228f,
    0.01f, 0.005623413251903491f, 0.0031622776601683794f, 0.0017782794100389228f,
    0.001f, 0.0005623413251903491f, 0.00031622776601683794f, 0.00017782794100389228f
};

// ================= scratch (device globals) =================
__device__ float g_lambda;
__device__ float g_tmp1[MROWS * DDIM];
__device__ float g_h   [MROWS * DDIM];
__device__ float g_f2  [MROWS * DDIM];

// attention operands: plain fp16, [b,h,s,64] / [b,h,s,128]
#define QKELEM (BDIM*HH*SDIM*64)
__device__ __half g_q116[QKELEM], g_k116[QKELEM];
__device__ __half g_q216[QKELEM], g_k216[QKELEM];
__device__ __half g_v16[BDIM*HH*SDIM*128];

// fp16 staging (all weights plain single-term)
__device__ __half g_x16  [MROWS*DDIM];
__device__ __half g_attn16[MROWS*DDIM];
__device__ __half g_h16  [MROWS*DDIM];
__device__ __half g_ff116[MROWS*4*DDIM];
__device__ __half g_wqkvT16[3*DDIM*DDIM];
__device__ __half g_woutT16[DDIM*DDIM];
__device__ __half g_w1T16[4*DDIM*DDIM];
__device__ __half g_w2T16[DDIM*4*DDIM];

// ================= helpers =================
__device__ __forceinline__ uint32_t smem_u32(const void* p) {
    uint32_t a;
    asm("{ .reg .u64 t; cvta.to.shared.u64 t, %1; cvt.u32.u64 %0, t; }" : "=r"(a) : "l"(p));
    return a;
}
__device__ __forceinline__ void cpasync16(uint32_t dst, const void* src) {
    asm volatile("cp.async.cg.shared.global [%0], [%1], 16;" :: "r"(dst), "l"(src));
}
__device__ __forceinline__ void cp_commit() { asm volatile("cp.async.commit_group;" ::: "memory"); }
__device__ __forceinline__ void ldm4(uint32_t* r, uint32_t addr) {
    asm volatile("ldmatrix.sync.aligned.m8n8.x4.shared.b16 {%0,%1,%2,%3}, [%4];"
        : "=r"(r[0]), "=r"(r[1]), "=r"(r[2]), "=r"(r[3]) : "r"(addr));
}
__device__ __forceinline__ void ldm4t(uint32_t* r, uint32_t addr) {
    asm volatile("ldmatrix.sync.aligned.m8n8.x4.trans.shared.b16 {%0,%1,%2,%3}, [%4];"
        : "=r"(r[0]), "=r"(r[1]), "=r"(r[2]), "=r"(r[3]) : "r"(addr));
}
__device__ __forceinline__ void mma16816h(float* c, const uint32_t* a, uint32_t b0, uint32_t b1) {
    asm volatile("mma.sync.aligned.m16n8k16.row.col.f32.f16.f16.f32 "
        "{%0,%1,%2,%3}, {%4,%5,%6,%7}, {%8,%9}, {%0,%1,%2,%3};"
        : "+f"(c[0]), "+f"(c[1]), "+f"(c[2]), "+f"(c[3])
        : "r"(a[0]), "r"(a[1]), "r"(a[2]), "r"(a[3]), "r"(b0), "r"(b1));
}
__device__ __forceinline__ uint32_t packh(float a, float b) {
    __half2 t = __floats2half2_rn(a, b);
    return *(uint32_t*)&t;
}

// ================= lambda =================
__global__ void lambda_kernel(const float* __restrict__ lq1, const float* __restrict__ lk1,
                              const float* __restrict__ lq2, const float* __restrict__ lk2)
{
    int lane = threadIdx.x;
    float s1 = lq1[lane]*lk1[lane] + lq1[lane+32]*lk1[lane+32];
    float s2 = lq2[lane]*lk2[lane] + lq2[lane+32]*lk2[lane+32];
#pragma unroll
    for (int o = 16; o; o >>= 1) {
        s1 += __shfl_xor_sync(0xffffffffu, s1, o);
        s2 += __shfl_xor_sync(0xffffffffu, s2, o);
    }
    if (lane == 0) g_lambda = expf(s1) - expf(s2) + LAMBDA_INIT_F;
}

// ================= fp32 -> plain fp16 =================
__global__ __launch_bounds__(256) void split_f16_kernel(const float* __restrict__ in,
    __half* __restrict__ o, int n4)
{
    int i = blockIdx.x * 256 + threadIdx.x;
    if (i >= n4) return;
    float4 v = ((const float4*)in)[i];
    ((__half2*)o)[2*i]   = __floats2half2_rn(v.x, v.y);
    ((__half2*)o)[2*i+1] = __floats2half2_rn(v.z, v.w);
}

// ================= transpose: in[K,N] fp32 -> out[N,K] fp16 =================
__global__ __launch_bounds__(256) void transpose_f16_kernel(const float* __restrict__ in,
    __half* __restrict__ oh, int K, int N)
{
    __shared__ float t[32][33];
    const int k0 = blockIdx.y*32, n0 = blockIdx.x*32;
    const int tx = threadIdx.x, ty = threadIdx.y;
#pragma unroll
    for (int i = 0; i < 4; i++)
        t[ty + i*8][tx] = in[(size_t)(k0 + ty + i*8)*N + n0 + tx];
    __syncthreads();
#pragma unroll
    for (int i = 0; i < 4; i++) {
        int n = n0 + ty + i*8, k = k0 + tx;
        oh[(size_t)n*K + k] = __float2half(t[tx][ty + i*8]);
    }
}

// ================= mma.sync fp16 GEMM (R12 shape) with optional fused QKV epilogue ======
// Generic: C[M,N] = A[M,K] @ B[N,K]^T (+bias)(silu?)(+resid)
// qkv_mode: epilogue performs RoPE + head split + q2/k2 rmsnorm + V repack, writing
// directly to g_q116/g_k116/g_q216/g_k216/g_v16 (no intermediate qkv buffer).
#define FK_ROWB   144
#define F_TILE_B  (128*FK_ROWB)     // 18432
#define F_STAGE_B (2*F_TILE_B)      // 36864
#define GEMMF_SMEM (2*F_STAGE_B)    // 73728

__global__ __launch_bounds__(256, 2) void gemm_f16_kernel(
    const __half* __restrict__ Ah,
    const __half* __restrict__ Bh,
    float* __restrict__ Cf, __half* __restrict__ Ch16,
    int M, int N, int K,
    const float* __restrict__ bias, const float* __restrict__ resid, int act,
    int qkv_mode,
    const float* __restrict__ sigmas,
    const float* __restrict__ lnq_w, const float* __restrict__ lnq_b)
{
    extern __shared__ char smem[];
    const uint32_t sb = smem_u32(smem);
    const int tid = threadIdx.x;
    const int lane = tid & 31;
    const int wid = tid >> 5;
    const int bm = blockIdx.y * 128;
    const int bn = blockIdx.x * 128;
    const int wm = wid >> 2;
    const int wn = wid & 3;

    const int lrow  = tid >> 1;
    const int lhalf = (tid & 1) * 64;
    const size_t rowB = (size_t)K * 2;
    const char* gA  = (const char*)Ah + (size_t)(bm + lrow) * rowB + lhalf;
    const char* gBh = (const char*)Bh + (size_t)(bn + lrow) * rowB + lhalf;
    const uint32_t sdst = sb + (uint32_t)lrow * FK_ROWB + (uint32_t)lhalf;

    const int nChunks = K >> 6;

    {
#pragma unroll
        for (int j = 0; j < 4; j++) {
            cpasync16(sdst +            j*16, gA  + j*16);
            cpasync16(sdst + F_TILE_B + j*16, gBh + j*16);
        }
        cp_commit();
    }

    float acc[4][4][4];
#pragma unroll
    for (int i = 0; i < 4; i++)
#pragma unroll
        for (int j = 0; j < 4; j++)
#pragma unroll
            for (int k = 0; k < 4; k++) acc[i][j][k] = 0.f;

    const int lt = lane >> 3, lj = lane & 7;
    const uint32_t a_row = (uint32_t)(wm*64 + (lt & 1)*8 + lj) * FK_ROWB;
    const uint32_t a_col = (uint32_t)((lt >> 1) * 8) * 2u;
    const uint32_t b_row = (uint32_t)(wn*32 + (lt >> 1)*8 + lj) * FK_ROWB;
    const uint32_t b_col = (uint32_t)((lt & 1) * 8) * 2u;

    for (int c = 0; c < nChunks; c++) {
        asm volatile("cp.async.wait_group 0;" ::: "memory");
        __syncthreads();

        if (c + 1 < nChunks) {
            const uint32_t d = sdst + (uint32_t)((c + 1) & 1) * F_STAGE_B;
            const size_t go = (size_t)(c + 1) * 128;
#pragma unroll
            for (int j = 0; j < 4; j++) {
                cpasync16(d +            j*16, gA  + go + j*16);
                cpasync16(d + F_TILE_B + j*16, gBh + go + j*16);
            }
            cp_commit();
        }

        const uint32_t base = sb + (uint32_t)(c & 1) * F_STAGE_B;
#pragma unroll
        for (int ka = 0; ka < 4; ka++) {
            const uint32_t kofs = (uint32_t)ka * 32u;
            uint32_t bfh[2][4];
#pragma unroll
            for (int g = 0; g < 2; g++)
                ldm4(bfh[g], base + F_TILE_B + b_row + (uint32_t)g*16u*FK_ROWB + b_col + kofs);
#pragma unroll
            for (int ma = 0; ma < 4; ma++) {
                uint32_t af[4];
                ldm4(af, base + a_row + (uint32_t)ma*16u*FK_ROWB + a_col + kofs);
#pragma unroll
                for (int g = 0; g < 2; g++)
#pragma unroll
                    for (int hf = 0; hf < 2; hf++)
                        mma16816h(acc[ma][g*2 + hf], af, bfh[g][hf*2], bfh[g][hf*2+1]);
            }
        }
    }

    if (qkv_mode) {
        // ===== fused RoPE / split / rmsnorm / V-repack epilogue =====
        __syncthreads();                 // mainloop smem consumption complete
        float* sq = (float*)smem;        // 128-float reduction buffer
        const int rg = lane >> 2;
        const int cp = lane & 3;
        const int bb = bm >> 11;         // batch index (uniform per CTA)

        if (bn >= 2048) {
            // ---- V region: repack to [b,h,s,128] fp16 ----
            const int vc_base = bn - 2048 + wn*32;
#pragma unroll
            for (int ma = 0; ma < 4; ma++)
#pragma unroll
                for (int na = 0; na < 4; na++) {
                    const int vc = vc_base + na*8 + 2*cp;
                    const int hh = vc >> 7, e = vc & 127;
#pragma unroll
                    for (int half = 0; half < 2; half++) {
                        const int r = bm + wm*64 + ma*16 + rg + half*8;
                        const int ssi = r & 2047;
                        __half* dp = g_v16 + (((size_t)bb*HH + hh)*SDIM + ssi)*128 + e;
                        *(__half2*)dp = __floats2half2_rn(acc[ma][na][half*2], acc[ma][na][half*2+1]);
                    }
                }
        } else {
            // ---- Q/K region ----
            const int which = (bn >= 1024) ? 1 : 0;
            const int qc_base = bn - which*1024;
            const int hh = qc_base >> 7;        // head (tile covers h2 pair {2h, 2h+1})
            const int comp = wn >> 1;           // 0: q1/k1, 1: q2/k2
            const int rot  = !(wn & 1);         // dims [0,32) rotated
            const int dbase = (wn & 1) * 32;

            // RoPE rotation (thread-local adjacent pair)
            if (rot) {
#pragma unroll
                for (int ma = 0; ma < 4; ma++)
#pragma unroll
                    for (int half = 0; half < 2; half++) {
                        const int r = bm + wm*64 + ma*16 + rg + half*8;
                        const float fs = (float)(r & 2047);
#pragma unroll
                        for (int na = 0; na < 4; na++) {
                            const int j = (dbase + na*8 + 2*cp) >> 1;
                            float sn, cs;
                            sincosf(fs * INVFREQ[j], &sn, &cs);
                            float a0 = acc[ma][na][half*2];
                            float a1 = acc[ma][na][half*2+1];
                            acc[ma][na][half*2]   = a0*cs - a1*sn;
                            acc[ma][na][half*2+1] = a1*cs + a0*sn;
                        }
                    }
            }
            // + sigma for comp1
            if (comp) {
#pragma unroll
                for (int na = 0; na < 4; na++) {
                    const int d0 = dbase + na*8 + 2*cp;
                    const float sg0 = sigmas[bb*64 + d0];
                    const float sg1 = sigmas[bb*64 + d0 + 1];
#pragma unroll
                    for (int ma = 0; ma < 4; ma++)
#pragma unroll
                        for (int half = 0; half < 2; half++) {
                            acc[ma][na][half*2]   += sg0;
                            acc[ma][na][half*2+1] += sg1;
                        }
                }
            }
            // rmsnorm(64) for comp1: 4-lane shfl + warp-pair smem exchange
            float prt[4][2];
            if (comp) {
#pragma unroll
                for (int ma = 0; ma < 4; ma++)
#pragma unroll
                    for (int half = 0; half < 2; half++) {
                        float t = 0.f;
#pragma unroll
                        for (int na = 0; na < 4; na++)
                            t += acc[ma][na][half*2]*acc[ma][na][half*2]
                               + acc[ma][na][half*2+1]*acc[ma][na][half*2+1];
                        t += __shfl_xor_sync(0xffffffffu, t, 1);
                        t += __shfl_xor_sync(0xffffffffu, t, 2);
                        prt[ma][half] = t;
                    }
                if (wn == 2) {
#pragma unroll
                    for (int ma = 0; ma < 4; ma++)
#pragma unroll
                        for (int half = 0; half < 2; half++)
                            sq[wm*64 + ma*16 + rg + half*8] = prt[ma][half];
                }
            }
            __syncthreads();
            float rmsv[4][2];
            if (comp && wn == 3) {
#pragma unroll
                for (int ma = 0; ma < 4; ma++)
#pragma unroll
                    for (int half = 0; half < 2; half++) {
                        const int ri = wm*64 + ma*16 + rg + half*8;
                        float full = sq[ri] + prt[ma][half];
                        float rv = rsqrtf(full * (1.f/64.f) + 1e-8f);
                        rmsv[ma][half] = rv;
                        sq[ri] = rv;
                    }
            }
            __syncthreads();
            if (comp && wn == 2) {
#pragma unroll
                for (int ma = 0; ma < 4; ma++)
#pragma unroll
                    for (int half = 0; half < 2; half++)
                        rmsv[ma][half] = sq[wm*64 + ma*16 + rg + half*8];
            }
            // store
            __half* dst0 = comp ? (which ? g_k216 : g_q216)
                                : (which ? g_k116 : g_q116);
#pragma unroll
            for (int na = 0; na < 4; na++) {
                const int d0 = dbase + na*8 + 2*cp;
                float w0 = 1.f, w1 = 1.f, bq0 = 0.f, bq1 = 0.f;
                if (comp) {
                    w0 = lnq_w[d0]; w1 = lnq_w[d0+1];
                    bq0 = lnq_b[d0]; bq1 = lnq_b[d0+1];
                }
#pragma unroll
                for (int ma = 0; ma < 4; ma++)
#pragma unroll
                    for (int half = 0; half < 2; half++) {
                        const int r = bm + wm*64 + ma*16 + rg + half*8;
                        const int ssi = r & 2047;
                        float v0 = acc[ma][na][half*2];
                        float v1 = acc[ma][na][half*2+1];
                        if (comp) {
                            const float rv = rmsv[ma][half];
                            v0 = v0*rv*w0 + bq0;
                            v1 = v1*rv*w1 + bq1;
                        }
                        __half* dp = dst0 + (((size_t)bb*HH + hh)*SDIM + ssi)*64 + d0;
                        *(__half2*)dp = __floats2half2_rn(v0, v1);
                    }
            }
        }
        return;
    }

    // ===== generic epilogue =====
#pragma unroll
    for (int ma = 0; ma < 4; ma++)
#pragma unroll
        for (int na = 0; na < 4; na++) {
            const int r0 = bm + wm*64 + ma*16 + (lane >> 2);
            const int c0 = bn + wn*32 + na*8 + 2*(lane & 3);
#pragma unroll
            for (int half = 0; half < 2; half++) {
                const int r = r0 + half*8;
                float v0 = acc[ma][na][half*2 + 0];
                float v1 = acc[ma][na][half*2 + 1];
                if (bias) { v0 += bias[c0]; v1 += bias[c0 + 1]; }
                if (act) {
                    v0 = v0 / (1.f + __expf(-v0));
                    v1 = v1 / (1.f + __expf(-v1));
                }
                const size_t o = (size_t)r * N + c0;
                if (resid) { v0 += resid[o]; v1 += resid[o + 1]; }
                if (Cf) { float2 f2o; f2o.x = v0; f2o.y = v1; *(float2*)&Cf[o] = f2o; }
                if (Ch16) *(__half2*)&Ch16[o] = __floats2half2_rn(v0, v1);
            }
        }
}

// ================= tensor-core dual causal attention (plain fp16) + diff + rmsnorm =======
#define AKT_STRIDE 144
#define AVT_STRIDE 272
#define AQ_TILE 9216
#define AV_TILE 17408
#define A_QREG (2*AQ_TILE)               // 18432
#define AKV_STAGE (2*AQ_TILE + AV_TILE)  // 35840
#define ATT_SMEM (A_QREG + 2*AKV_STAGE)  // 90112
#define SCALE_L2E 0.18033688011112042f   // 0.125 * log2(e)

__global__ __launch_bounds__(256, 2) void attn_mma_kernel(
    const float* __restrict__ ln_w, const float* __restrict__ ln_b)
{
    extern __shared__ char smem[];
    const uint32_t sb = smem_u32(smem);
    const int tid = threadIdx.x, lane = tid & 31, wid = tid >> 5;
    const int br = wid >> 2, wr = wid & 3;
    const int qt = (int)gridDim.x - 1 - (int)blockIdx.x;   // heavy tiles first
    const int h = blockIdx.y, b = blockIdx.z;
    const int q0 = qt * 64;
    const int bh = b*HH + h;
    const size_t qkbase = (size_t)bh * SDIM * 64;
    const size_t vbase  = (size_t)bh * SDIM * 128;

    // prologue: Q tiles + stage 0 K/V
    {
        const int rq = (tid >> 3), jq = tid & 7;
#pragma unroll
        for (int u = 0; u < 4; u++) {
            const int row = rq + (u & 1)*32;
            const __half* src = (u < 2) ? g_q116 : g_q216;
            cpasync16(sb + (u >> 1)*AQ_TILE + row*AKT_STRIDE + jq*16,
                      src + qkbase + (size_t)(q0 + row)*64 + jq*8);
        }
        const uint32_t kb = sb + A_QREG;
#pragma unroll
        for (int u = 0; u < 4; u++) {
            const int row = rq + (u & 1)*32;
            const __half* src = (u < 2) ? g_k116 : g_k216;
            cpasync16(kb + (u >> 1)*AQ_TILE + row*AKT_STRIDE + jq*16,
                      src + qkbase + (size_t)row*64 + jq*8);
        }
        const uint32_t vb = kb + 2*AQ_TILE;
        const int rv = (tid >> 4), jv = tid & 15;
#pragma unroll
        for (int u = 0; u < 4; u++) {
            const int row = rv + u*16;
            cpasync16(vb + row*AVT_STRIDE + jv*16,
                      g_v16 + vbase + (size_t)row*128 + jv*8);
        }
        cp_commit();
    }

    const int lt = lane >> 3, lj = lane & 7;
    const uint32_t qa_off = (uint32_t)(wr*16 + (lt & 1)*8 + lj)*AKT_STRIDE + (uint32_t)(lt >> 1)*16;
    const uint32_t kb_off = (uint32_t)((lt >> 1)*8 + lj)*AKT_STRIDE + (uint32_t)(lt & 1)*16;
    const uint32_t vb_off = (uint32_t)((lt & 1)*8 + lj)*AVT_STRIDE + (uint32_t)(lt >> 1)*16;
    const uint32_t qbase = sb + br*AQ_TILE;

    float acc[16][4];
#pragma unroll
    for (int n = 0; n < 16; n++)
#pragma unroll
        for (int c = 0; c < 4; c++) acc[n][c] = 0.f;
    float m0 = -1e30f, m1 = -1e30f, l0 = 0.f, l1 = 0.f;

    const int row_l = wr*16 + (lane >> 2);
    const int nIter = qt + 1;

    for (int kt = 0; kt < nIter; kt++) {
        if (kt + 1 < nIter) {
            const int k0n = (kt + 1) * 64;
            const uint32_t kb = sb + A_QREG + ((kt + 1) & 1)*AKV_STAGE;
            const int rq = (tid >> 3), jq = tid & 7;
#pragma unroll
            for (int u = 0; u < 4; u++) {
                const int row = rq + (u & 1)*32;
                const __half* src = (u < 2) ? g_k116 : g_k216;
                cpasync16(kb + (u >> 1)*AQ_TILE + row*AKT_STRIDE + jq*16,
                          src + qkbase + (size_t)(k0n + row)*64 + jq*8);
            }
            const uint32_t vb = kb + 2*AQ_TILE;
            const int rv = (tid >> 4), jv = tid & 15;
#pragma unroll
            for (int u = 0; u < 4; u++) {
                const int row = rv + u*16;
                cpasync16(vb + row*AVT_STRIDE + jv*16,
                          g_v16 + vbase + (size_t)(k0n + row)*128 + jv*8);
            }
            cp_commit();
            asm volatile("cp.async.wait_group 1;" ::: "memory");
        } else {
            asm volatile("cp.async.wait_group 0;" ::: "memory");
        }
        __syncthreads();

        const uint32_t stg = sb + A_QREG + (kt & 1)*AKV_STAGE;
        const uint32_t k_base = stg + br*AQ_TILE;
        const uint32_t v_base = stg + 2*AQ_TILE;

        float sacc[8][4];
#pragma unroll
        for (int g = 0; g < 8; g++)
#pragma unroll
            for (int c = 0; c < 4; c++) sacc[g][c] = 0.f;
#pragma unroll
        for (int ka = 0; ka < 4; ka++) {
            uint32_t ah[4];
            ldm4(ah, qbase + qa_off + ka*32);
#pragma unroll
            for (int g2 = 0; g2 < 4; g2++) {
                uint32_t bh4[4];
                ldm4(bh4, k_base + g2*(16*AKT_STRIDE) + kb_off + ka*32);
#pragma unroll
                for (int hf = 0; hf < 2; hf++)
                    mma16816h(sacc[g2*2 + hf], ah, bh4[hf*2], bh4[hf*2+1]);
            }
        }

        const bool diag = (kt == qt);
        float t0 = -1e30f, t1 = -1e30f;
#pragma unroll
        for (int g = 0; g < 8; g++) {
            const int cb = g*8 + (lane & 3)*2;
#pragma unroll
            for (int c = 0; c < 4; c++) {
                float s = sacc[g][c] * SCALE_L2E;
                if (diag) {
                    const int rr = row_l + (c >= 2 ? 8 : 0);
                    const int cc = cb + (c & 1);
                    if (cc > rr) s = -1e30f;
                }
                sacc[g][c] = s;
            }
            t0 = fmaxf(t0, fmaxf(sacc[g][0], sacc[g][1]));
            t1 = fmaxf(t1, fmaxf(sacc[g][2], sacc[g][3]));
        }
        t0 = fmaxf(t0, __shfl_xor_sync(0xffffffffu, t0, 1));
        t0 = fmaxf(t0, __shfl_xor_sync(0xffffffffu, t0, 2));
        t1 = fmaxf(t1, __shfl_xor_sync(0xffffffffu, t1, 1));
        t1 = fmaxf(t1, __shfl_xor_sync(0xffffffffu, t1, 2));
        const float mn0 = fmaxf(m0, t0), mn1 = fmaxf(m1, t1);
        const float alpha0 = exp2f(m0 - mn0), alpha1 = exp2f(m1 - mn1);
        m0 = mn0; m1 = mn1;

        float rs0 = 0.f, rs1 = 0.f;
#pragma unroll
        for (int g = 0; g < 8; g++) {
            float p0 = exp2f(sacc[g][0] - mn0);
            float p1 = exp2f(sacc[g][1] - mn0);
            float p2 = exp2f(sacc[g][2] - mn1);
            float p3 = exp2f(sacc[g][3] - mn1);
            sacc[g][0] = p0; sacc[g][1] = p1; sacc[g][2] = p2; sacc[g][3] = p3;
            rs0 += p0 + p1; rs1 += p2 + p3;
        }
        rs0 += __shfl_xor_sync(0xffffffffu, rs0, 1);
        rs0 += __shfl_xor_sync(0xffffffffu, rs0, 2);
        rs1 += __shfl_xor_sync(0xffffffffu, rs1, 1);
        rs1 += __shfl_xor_sync(0xffffffffu, rs1, 2);
        l0 = l0*alpha0 + rs0;
        l1 = l1*alpha1 + rs1;

#pragma unroll
        for (int n = 0; n < 16; n++) {
            acc[n][0] *= alpha0; acc[n][1] *= alpha0;
            acc[n][2] *= alpha1; acc[n][3] *= alpha1;
        }

#pragma unroll
        for (int ka = 0; ka < 4; ka++) {
            uint32_t ph[4];
#pragma unroll
            for (int half = 0; half < 2; half++) {
                const int g = 2*ka + half;
                ph[half*2 + 0] = packh(sacc[g][0], sacc[g][1]);
                ph[half*2 + 1] = packh(sacc[g][2], sacc[g][3]);
            }
#pragma unroll
            for (int np = 0; np < 8; np++) {
                uint32_t vh4[4];
                ldm4t(vh4, v_base + ka*(16*AVT_STRIDE) + vb_off + np*32);
#pragma unroll
                for (int hf = 0; hf < 2; hf++)
                    mma16816h(acc[np*2 + hf], ph, vh4[hf*2], vh4[hf*2+1]);
            }
        }
        __syncthreads();
    }

    const float inv0 = 1.f / l0, inv1 = 1.f / l1;
#pragma unroll
    for (int n = 0; n < 16; n++) {
        acc[n][0] *= inv0; acc[n][1] *= inv0;
        acc[n][2] *= inv1; acc[n][3] *= inv1;
    }

    float* sO = (float*)smem;
    const int rl = row_l, rh = row_l + 8;
    __syncthreads();
    if (br == 1) {
#pragma unroll
        for (int n = 0; n < 16; n++) {
            const int c = n*8 + (lane & 3)*2;
            float2 a; a.x = acc[n][0]; a.y = acc[n][1];
            float2 bvv; bvv.x = acc[n][2]; bvv.y = acc[n][3];
            *(float2*)&sO[rl*128 + c] = a;
            *(float2*)&sO[rh*128 + c] = bvv;
        }
    }
    __syncthreads();
    if (br == 0) {
        const float lam = g_lambda;
        const float osc = 1.f - LAMBDA_INIT_F;
        float ssq0 = 0.f, ssq1 = 0.f;
#pragma unroll
        for (int n = 0; n < 16; n++) {
            const int c = n*8 + (lane & 3)*2;
            float2 o2l = *(float2*)&sO[rl*128 + c];
            float2 o2h = *(float2*)&sO[rh*128 + c];
            acc[n][0] -= lam*o2l.x; acc[n][1] -= lam*o2l.y;
            acc[n][2] -= lam*o2h.x; acc[n][3] -= lam*o2h.y;
            ssq0 += acc[n][0]*acc[n][0] + acc[n][1]*acc[n][1];
            ssq1 += acc[n][2]*acc[n][2] + acc[n][3]*acc[n][3];
        }
        ssq0 += __shfl_xor_sync(0xffffffffu, ssq0, 1);
        ssq0 += __shfl_xor_sync(0xffffffffu, ssq0, 2);
        ssq1 += __shfl_xor_sync(0xffffffffu, ssq1, 1);
        ssq1 += __shfl_xor_sync(0xffffffffu, ssq1, 2);
        const float rms0 = rsqrtf(ssq0 * (1.f/128.f) + 1e-8f);
        const float rms1 = rsqrtf(ssq1 * (1.f/128.f) + 1e-8f);
        const size_t ob_l = ((size_t)(b*SDIM + q0 + rl))*DDIM + h*128;
        const size_t ob_h = ((size_t)(b*SDIM + q0 + rh))*DDIM + h*128;
#pragma unroll
        for (int n = 0; n < 16; n++) {
            const int c = n*8 + (lane & 3)*2;
            float w0 = __ldg(&ln_w[c]), w1 = __ldg(&ln_w[c+1]);
            float bb0 = __ldg(&ln_b[c]), bb1 = __ldg(&ln_b[c+1]);
            float v0 = (acc[n][0]*rms0*w0 + bb0) * osc;
            float v1 = (acc[n][1]*rms0*w1 + bb1) * osc;
            float v2 = (acc[n][2]*rms1*w0 + bb0) * osc;
            float v3 = (acc[n][3]*rms1*w1 + bb1) * osc;
            *(__half2*)&g_attn16[ob_l + c] = __floats2half2_rn(v0, v1);
            *(__half2*)&g_attn16[ob_h + c] = __floats2half2_rn(v2, v3);
        }
    }
}

// ================= layernorm over 1024 (+ optional plain fp16 out) =================
__global__ __launch_bounds__(256) void layernorm_kernel(
    const float* __restrict__ in, const float* __restrict__ w, const float* __restrict__ bb,
    float* __restrict__ out, __half* __restrict__ oh16)
{
    __shared__ float red1[8], red2[8];
    const int row = blockIdx.x;
    const float* x = in + (size_t)row * DDIM;
    float v[4];
    float s = 0.f, s2 = 0.f;
#pragma unroll
    for (int it = 0; it < 4; it++) {
        float t = x[threadIdx.x + it*256];
        v[it] = t; s += t; s2 += t*t;
    }
#pragma unroll
    for (int o = 16; o; o >>= 1) {
        s  += __shfl_xor_sync(0xffffffffu, s,  o);
        s2 += __shfl_xor_sync(0xffffffffu, s2, o);
    }
    const int lane = threadIdx.x & 31, wp = threadIdx.x >> 5;
    if (lane == 0) { red1[wp] = s; red2[wp] = s2; }
    __syncthreads();
    if (wp == 0) {
        s  = (lane < 8) ? red1[lane] : 0.f;
        s2 = (lane < 8) ? red2[lane] : 0.f;
#pragma unroll
        for (int o = 4; o; o >>= 1) {
            s  += __shfl_xor_sync(0xffffffffu, s,  o);
            s2 += __shfl_xor_sync(0xffffffffu, s2, o);
        }
        if (lane == 0) { red1[0] = s * (1.f/1024.f); red2[0] = s2 * (1.f/1024.f); }
    }
    __syncthreads();
    const float mean = red1[0];
    const float var = red2[0] - mean*mean;
    const float rstd = rsqrtf(var + 1e-5f);
#pragma unroll
    for (int it = 0; it < 4; it++) {
        int c = threadIdx.x + it*256;
        size_t idx = (size_t)row*DDIM + c;
        float y = (v[it] - mean)*rstd*w[c] + bb[c];
        out[idx] = y;
        if (oh16) oh16[idx] = __float2half(y);
    }
}

// ================= launch =================
extern "C" void kernel_launch(void* const* d_in, const int* in_sizes, int n_in,
                              void* d_out, int out_size)
{
    (void)in_sizes; (void)n_in; (void)out_size;
    const float* x      = (const float*)d_in[0];
    const float* sigmas = (const float*)d_in[1];
    const float* w_qkv  = (const float*)d_in[2];
    const float* w_out  = (const float*)d_in[3];
    const float* lq1    = (const float*)d_in[4];
    const float* lk1    = (const float*)d_in[5];
    const float* lq2    = (const float*)d_in[6];
    const float* lk2    = (const float*)d_in[7];
    const float* ln_w   = (const float*)d_in[8];
    const float* ln_b   = (const float*)d_in[9];
    const float* lnq_w  = (const float*)d_in[10];
    const float* lnq_b  = (const float*)d_in[11];
    const float* ln1_w  = (const float*)d_in[12];
    const float* ln1_b  = (const float*)d_in[13];
    const float* ln2_w  = (const float*)d_in[14];
    const float* ln2_b  = (const float*)d_in[15];
    const float* w1     = (const float*)d_in[16];
    const float* b1     = (const float*)d_in[17];
    const float* w2     = (const float*)d_in[18];
    const float* b2     = (const float*)d_in[19];
    float* out = (float*)d_out;

    void *p_tmp1, *p_h, *p_f2;
    void *p_x16, *p_attn16, *p_h16, *p_ff116;
    void *p_wqkv, *p_wout, *p_w1, *p_w2;
    cudaGetSymbolAddress(&p_tmp1, g_tmp1);
    cudaGetSymbolAddress(&p_h,    g_h);
    cudaGetSymbolAddress(&p_f2,   g_f2);
    cudaGetSymbolAddress(&p_x16, g_x16);
    cudaGetSymbolAddress(&p_attn16, g_attn16);
    cudaGetSymbolAddress(&p_h16, g_h16);
    cudaGetSymbolAddress(&p_ff116, g_ff116);
    cudaGetSymbolAddress(&p_wqkv, g_wqkvT16);
    cudaGetSymbolAddress(&p_wout, g_woutT16);
    cudaGetSymbolAddress(&p_w1, g_w1T16);
    cudaGetSymbolAddress(&p_w2, g_w2T16);

    cudaFuncSetAttribute(gemm_f16_kernel, cudaFuncAttributeMaxDynamicSharedMemorySize, GEMMF_SMEM);
    cudaFuncSetAttribute(attn_mma_kernel, cudaFuncAttributeMaxDynamicSharedMemorySize, ATT_SMEM);

    // prep for qkv
    lambda_kernel<<<1, 32>>>(lq1, lk1, lq2, lk2);
    split_f16_kernel<<<(MROWS*DDIM/4 + 255)/256, 256>>>(x, (__half*)p_x16, MROWS*DDIM/4);
    transpose_f16_kernel<<<dim3(3072/32, 1024/32), dim3(32,8)>>>(w_qkv, (__half*)p_wqkv, 1024, 3072);

    // qkv = x @ w_qkv with FUSED rope/split/rmsnorm/V-repack epilogue
    gemm_f16_kernel<<<dim3(3072/128, 4096/128), 256, GEMMF_SMEM>>>(
        (const __half*)p_x16, (const __half*)p_wqkv,
        nullptr, nullptr, MROWS, 3072, 1024, nullptr, nullptr, 0,
        1, sigmas, lnq_w, lnq_b);

    attn_mma_kernel<<<dim3(SDIM/64, HH, BDIM), 256, ATT_SMEM>>>(ln_w, ln_b);

    // remaining weight transposes
    transpose_f16_kernel<<<dim3(1024/32, 1024/32), dim3(32,8)>>>(w_out, (__half*)p_wout, 1024, 1024);
    transpose_f16_kernel<<<dim3(4096/32, 1024/32), dim3(32,8)>>>(w1, (__half*)p_w1, 1024, 4096);
    transpose_f16_kernel<<<dim3(1024/32, 4096/32), dim3(32,8)>>>(w2, (__half*)p_w2, 4096, 1024);

    // tmp1 = attn @ w_out + x
    gemm_f16_kernel<<<dim3(1024/128, 4096/128), 256, GEMMF_SMEM>>>(
        (const __half*)p_attn16, (const __half*)p_wout,
        (float*)p_tmp1, nullptr, MROWS, 1024, 1024, nullptr, x, 0,
        0, nullptr, nullptr, nullptr);

    layernorm_kernel<<<MROWS, 256>>>((const float*)p_tmp1, ln1_w, ln1_b,
        (float*)p_h, (__half*)p_h16);

    // ff1 = silu(h @ w1 + b1)
    gemm_f16_kernel<<<dim3(4096/128, 4096/128), 256, GEMMF_SMEM>>>(
        (const __half*)p_h16, (const __half*)p_w1,
        nullptr, (__half*)p_ff116, MROWS, 4096, 1024, b1, nullptr, 1,
        0, nullptr, nullptr, nullptr);

    // f2 = ff1 @ w2 + b2 + h
    gemm_f16_kernel<<<dim3(1024/128, 4096/128), 256, GEMMF_SMEM>>>(
        (const __half*)p_ff116, (const __half*)p_w2,
        (float*)p_f2, nullptr, MROWS, 1024, 4096, b2, (const float*)p_h, 0,
        0, nullptr, nullptr, nullptr);

    layernorm_kernel<<<MROWS, 256>>>((const float*)p_f2, ln2_w, ln2_b, out, nullptr);
}